// round 6
// baseline (speedup 1.0000x reference)
#include <cuda_runtime.h>
#include <cuda_bf16.h>
#include <cstdint>

// Problem dims (fixed for this dataset)
#define MAXN 100000
#define MAXE 1600000
#define FIN  784
#define D1   128
#define D2   256

// ---------------- scratch (device globals; no allocs allowed) ----------------
__device__ float g_h1[(size_t)MAXN * D1];   // x@W1 (pre-activation)
__device__ float g_g1[(size_t)MAXN * D1];   // relu(gat1)
__device__ float g_h2[(size_t)MAXN * D2];   // g1@W2
__device__ float g_g2[(size_t)MAXN * D2];   // relu(gat2)
__device__ float g_h3[(size_t)MAXN * 2];    // g2@W3
__device__ float g_as[MAXN];                // alpha_src per node (reused per layer)
__device__ float g_ad[MAXN];                // alpha_dst per node
__device__ int   g_counts[MAXN];
__device__ int   g_rowptr[MAXN + 1];
__device__ int   g_colsrc[MAXE];

__device__ __forceinline__ float leaky(float x) { return x > 0.f ? x : 0.2f * x; }

// ---------------- CSR build (edge_index is INT32: jax x64 is disabled) -------
__global__ void hist_kernel(const int* __restrict__ ei, int E) {
    int i = blockIdx.x * blockDim.x + threadIdx.x;
    if (i < E) {
        int d = ei[E + i];
        atomicAdd(&g_counts[d], 1);
    }
}

__global__ void scan_kernel(int N) {
    __shared__ int sums[1024];
    int t = threadIdx.x;
    int chunk = (N + 1023) >> 10;
    int beg = t * chunk, end = min(beg + chunk, N);
    int s = 0;
    for (int i = beg; i < end; i++) s += g_counts[i];
    sums[t] = s;
    __syncthreads();
    for (int off = 1; off < 1024; off <<= 1) {
        int v = (t >= off) ? sums[t - off] : 0;
        __syncthreads();
        sums[t] += v;
        __syncthreads();
    }
    int run = (t == 0) ? 0 : sums[t - 1];
    for (int i = beg; i < end; i++) { g_rowptr[i] = run; run += g_counts[i]; }
    if (t == 0) g_rowptr[N] = sums[1023];
}

__global__ void scatter_kernel(const int* __restrict__ ei, int E) {
    int i = blockIdx.x * blockDim.x + threadIdx.x;
    if (i < E) {
        int s = ei[i];
        int d = ei[E + i];
        int pos = g_rowptr[d] + atomicAdd(&g_counts[d], 1);
        g_colsrc[pos] = s;
    }
}

// ---------------- SGEMM: C[M,N] = A[M,K] @ B[K,N], row-major ----------------
__global__ void __launch_bounds__(256)
sgemm_kernel(const float* __restrict__ A, const float* __restrict__ B,
             float* __restrict__ C, int M, int N, int K) {
    constexpr int BM = 128, BN = 128, BK = 8;
    __shared__ float As[BK][BM];
    __shared__ float Bs[BK][BN];
    int tid = threadIdx.x;
    int tx = tid & 15;   // 0..15 (col group)
    int ty = tid >> 4;   // 0..15 (row group)
    int m0 = blockIdx.x * BM;
    int n0 = blockIdx.y * BN;

    float acc[8][8];
#pragma unroll
    for (int i = 0; i < 8; i++)
#pragma unroll
        for (int j = 0; j < 8; j++) acc[i][j] = 0.f;

    int a_row = tid >> 1;          // 0..127
    int a_col = (tid & 1) << 2;    // 0 or 4
    int b_row = tid >> 5;          // 0..7
    int b_col = (tid & 31) << 2;   // 0..124

    for (int k0 = 0; k0 < K; k0 += BK) {
        float4 av = make_float4(0.f, 0.f, 0.f, 0.f);
        int gr = m0 + a_row;
        if (gr < M) av = *(const float4*)(A + (size_t)gr * K + k0 + a_col);
        As[a_col + 0][a_row] = av.x;
        As[a_col + 1][a_row] = av.y;
        As[a_col + 2][a_row] = av.z;
        As[a_col + 3][a_row] = av.w;
        *(float4*)(&Bs[b_row][b_col]) =
            *(const float4*)(B + (size_t)(k0 + b_row) * N + n0 + b_col);
        __syncthreads();
#pragma unroll
        for (int kk = 0; kk < BK; kk++) {
            float ar[8], br[8];
            *(float4*)(ar)     = *(float4*)(&As[kk][ty * 8]);
            *(float4*)(ar + 4) = *(float4*)(&As[kk][ty * 8 + 4]);
            *(float4*)(br)     = *(float4*)(&Bs[kk][tx * 8]);
            *(float4*)(br + 4) = *(float4*)(&Bs[kk][tx * 8 + 4]);
#pragma unroll
            for (int i = 0; i < 8; i++)
#pragma unroll
                for (int j = 0; j < 8; j++)
                    acc[i][j] = fmaf(ar[i], br[j], acc[i][j]);
        }
        __syncthreads();
    }
#pragma unroll
    for (int i = 0; i < 8; i++) {
        int gr = m0 + ty * 8 + i;
        if (gr < M) {
            float4* cp = (float4*)(C + (size_t)gr * N + n0 + tx * 8);
            cp[0] = make_float4(acc[i][0], acc[i][1], acc[i][2], acc[i][3]);
            cp[1] = make_float4(acc[i][4], acc[i][5], acc[i][6], acc[i][7]);
        }
    }
}

// ---------------- alpha_src / alpha_dst: per-node dot products ----------------
template <int D>
__global__ void alpha_kernel(const float* __restrict__ h,
                             const float* __restrict__ a_s,
                             const float* __restrict__ a_d, int N) {
    int v = (blockIdx.x * blockDim.x + threadIdx.x) >> 5;
    if (v >= N) return;
    int lane = threadIdx.x & 31;
    const float4* hv = (const float4*)(h + (size_t)v * D);
    const float4* s4 = (const float4*)a_s;
    const float4* d4 = (const float4*)a_d;
    float ds = 0.f, dd = 0.f;
#pragma unroll
    for (int i = 0; i < D / 128; i++) {
        float4 hh = hv[lane + 32 * i];
        float4 aa = s4[lane + 32 * i];
        float4 bb = d4[lane + 32 * i];
        ds += hh.x * aa.x + hh.y * aa.y + hh.z * aa.z + hh.w * aa.w;
        dd += hh.x * bb.x + hh.y * bb.y + hh.z * bb.z + hh.w * bb.w;
    }
    for (int o = 16; o; o >>= 1) {
        ds += __shfl_xor_sync(~0u, ds, o);
        dd += __shfl_xor_sync(~0u, dd, o);
    }
    if (lane == 0) { g_as[v] = ds; g_ad[v] = dd; }
}

// ---------------- fused GAT aggregation (segment softmax + weighted sum) ----------------
// one warp per destination node; CSR gather; no atomics
template <int D, bool RELU>
__global__ void aggregate_kernel(const float* __restrict__ h,
                                 const float* __restrict__ bias,
                                 float* __restrict__ out, int N) {
    int v = (blockIdx.x * blockDim.x + threadIdx.x) >> 5;
    if (v >= N) return;
    int lane = threadIdx.x & 31;
    float adv = g_ad[v];
    float e_self = leaky(g_as[v] + adv);
    int beg = g_rowptr[v], end = g_rowptr[v + 1];

    // pass 1: max
    float m = e_self;
    for (int j = beg + lane; j < end; j += 32)
        m = fmaxf(m, leaky(g_as[g_colsrc[j]] + adv));
    for (int o = 16; o; o >>= 1) m = fmaxf(m, __shfl_xor_sync(~0u, m, o));

    // pass 2: sum of exp
    float s = 0.f;
    for (int j = beg + lane; j < end; j += 32)
        s += __expf(leaky(g_as[g_colsrc[j]] + adv) - m);
    for (int o = 16; o; o >>= 1) s += __shfl_xor_sync(~0u, s, o);
    float wself = __expf(e_self - m);
    s += wself;
    float invs = 1.f / s;

    // pass 3: weighted accumulate (lanes split feature dim, edges sequential)
    constexpr int V = D / 128;
    float4 acc[V];
    const float4* hv = (const float4*)(h + (size_t)v * D);
#pragma unroll
    for (int i = 0; i < V; i++) {
        float4 t = hv[lane + 32 * i];
        acc[i].x = wself * t.x; acc[i].y = wself * t.y;
        acc[i].z = wself * t.z; acc[i].w = wself * t.w;
    }
    for (int j = beg; j < end; j++) {
        int srcid = g_colsrc[j];
        float w = __expf(leaky(g_as[srcid] + adv) - m);
        const float4* hs = (const float4*)(h + (size_t)srcid * D);
#pragma unroll
        for (int i = 0; i < V; i++) {
            float4 t = hs[lane + 32 * i];
            acc[i].x = fmaf(w, t.x, acc[i].x);
            acc[i].y = fmaf(w, t.y, acc[i].y);
            acc[i].z = fmaf(w, t.z, acc[i].z);
            acc[i].w = fmaf(w, t.w, acc[i].w);
        }
    }
    const float4* b4 = (const float4*)bias;
    float4* o4 = (float4*)(out + (size_t)v * D);
#pragma unroll
    for (int i = 0; i < V; i++) {
        float4 b = b4[lane + 32 * i];
        float4 r;
        r.x = acc[i].x * invs + b.x;
        r.y = acc[i].y * invs + b.y;
        r.z = acc[i].z * invs + b.z;
        r.w = acc[i].w * invs + b.w;
        if (RELU) {
            r.x = fmaxf(r.x, 0.f); r.y = fmaxf(r.y, 0.f);
            r.z = fmaxf(r.z, 0.f); r.w = fmaxf(r.w, 0.f);
        }
        o4[lane + 32 * i] = r;
    }
}

// ---------------- layer 3 projection (256 -> 2) + its alphas ----------------
__global__ void layer3_kernel(const float* __restrict__ g2,
                              const float* __restrict__ W3,
                              const float* __restrict__ a3s,
                              const float* __restrict__ a3d, int N) {
    int v = (blockIdx.x * blockDim.x + threadIdx.x) >> 5;
    if (v >= N) return;
    int lane = threadIdx.x & 31;
    const float* row = g2 + (size_t)v * D2;
    float c0 = 0.f, c1 = 0.f;
#pragma unroll
    for (int i = 0; i < D2 / 32; i++) {
        int k = lane + 32 * i;
        float hv = row[k];
        c0 = fmaf(hv, W3[2 * k], c0);
        c1 = fmaf(hv, W3[2 * k + 1], c1);
    }
    for (int o = 16; o; o >>= 1) {
        c0 += __shfl_xor_sync(~0u, c0, o);
        c1 += __shfl_xor_sync(~0u, c1, o);
    }
    if (lane == 0) {
        g_h3[2 * v] = c0;
        g_h3[2 * v + 1] = c1;
        g_as[v] = c0 * a3s[0] + c1 * a3s[1];
        g_ad[v] = c0 * a3d[0] + c1 * a3d[1];
    }
}

// ---------------- layer 3 aggregation + final class softmax ----------------
__global__ void final_kernel(const float* __restrict__ b3, float* __restrict__ out, int N) {
    int v = (blockIdx.x * blockDim.x + threadIdx.x) >> 5;
    if (v >= N) return;
    int lane = threadIdx.x & 31;
    float adv = g_ad[v];
    float e_self = leaky(g_as[v] + adv);
    int beg = g_rowptr[v], end = g_rowptr[v + 1];

    float m = e_self;
    for (int j = beg + lane; j < end; j += 32)
        m = fmaxf(m, leaky(g_as[g_colsrc[j]] + adv));
    for (int o = 16; o; o >>= 1) m = fmaxf(m, __shfl_xor_sync(~0u, m, o));

    float s = 0.f, a0 = 0.f, a1 = 0.f;
    for (int j = beg + lane; j < end; j += 32) {
        int srcid = g_colsrc[j];
        float w = __expf(leaky(g_as[srcid] + adv) - m);
        s += w;
        a0 = fmaf(w, g_h3[2 * srcid], a0);
        a1 = fmaf(w, g_h3[2 * srcid + 1], a1);
    }
    for (int o = 16; o; o >>= 1) {
        s  += __shfl_xor_sync(~0u, s, o);
        a0 += __shfl_xor_sync(~0u, a0, o);
        a1 += __shfl_xor_sync(~0u, a1, o);
    }
    if (lane == 0) {
        float wself = __expf(e_self - m);
        s += wself;
        a0 += wself * g_h3[2 * v];
        a1 += wself * g_h3[2 * v + 1];
        float invs = 1.f / s;
        float o0 = a0 * invs + b3[0];
        float o1 = a1 * invs + b3[1];
        float mm = fmaxf(o0, o1);
        float z0 = __expf(o0 - mm);
        float z1 = __expf(o1 - mm);
        float zs = z0 + z1;
        out[2 * v]     = z0 / zs;
        out[2 * v + 1] = z1 / zs;
    }
}

// ---------------- launch ----------------
extern "C" void kernel_launch(void* const* d_in, const int* in_sizes, int n_in,
                              void* d_out, int out_size) {
    const float* x   = (const float*)d_in[0];
    const int*   ei  = (const int*)d_in[1];    // int32! (jax x64 disabled)
    // d_in[2] = batch (unused)
    const float* W1  = (const float*)d_in[3];
    const float* a1s = (const float*)d_in[4];
    const float* a1d = (const float*)d_in[5];
    const float* b1  = (const float*)d_in[6];
    const float* W2  = (const float*)d_in[7];
    const float* a2s = (const float*)d_in[8];
    const float* a2d = (const float*)d_in[9];
    const float* b2  = (const float*)d_in[10];
    const float* W3  = (const float*)d_in[11];
    const float* a3s = (const float*)d_in[12];
    const float* a3d = (const float*)d_in[13];
    const float* b3  = (const float*)d_in[14];

    int N = in_sizes[2];        // batch has one entry per node
    int E = in_sizes[1] / 2;

    float *h1, *g1, *h2, *g2;
    int* counts;
    cudaGetSymbolAddress((void**)&h1, g_h1);
    cudaGetSymbolAddress((void**)&g1, g_g1);
    cudaGetSymbolAddress((void**)&h2, g_h2);
    cudaGetSymbolAddress((void**)&g2, g_g2);
    cudaGetSymbolAddress((void**)&counts, g_counts);

    int eb = (E + 255) / 256;
    int nodeWarpBlocks = (N + 7) / 8;   // 8 warps / 256-thread block
    int gemmRows = (N + 127) / 128;

    // CSR build (shared by all 3 layers)
    cudaMemsetAsync(counts, 0, N * sizeof(int));
    hist_kernel<<<eb, 256>>>(ei, E);
    scan_kernel<<<1, 1024>>>(N);
    cudaMemsetAsync(counts, 0, N * sizeof(int));
    scatter_kernel<<<eb, 256>>>(ei, E);

    // layer 1
    sgemm_kernel<<<dim3(gemmRows, 1), 256>>>(x, W1, h1, N, D1, FIN);
    alpha_kernel<D1><<<nodeWarpBlocks, 256>>>(h1, a1s, a1d, N);
    aggregate_kernel<D1, true><<<nodeWarpBlocks, 256>>>(h1, b1, g1, N);

    // layer 2
    sgemm_kernel<<<dim3(gemmRows, 2), 256>>>(g1, W2, h2, N, D2, D1);
    alpha_kernel<D2><<<nodeWarpBlocks, 256>>>(h2, a2s, a2d, N);
    aggregate_kernel<D2, true><<<nodeWarpBlocks, 256>>>(h2, b2, g2, N);

    // layer 3 + output softmax
    layer3_kernel<<<nodeWarpBlocks, 256>>>(g2, W3, a3s, a3d, N);
    final_kernel<<<nodeWarpBlocks, 256>>>(b3, (float*)d_out, N);
}